// round 14
// baseline (speedup 1.0000x reference)
#include <cuda_runtime.h>
#include <math.h>
#include <float.h>

// ---------------------------------------------------------------------------
// EceLabelShift: equal-mass-bin ECE with label-shift weighting.
// R12: EVERYTHING in one persistent kernel (148 blocks x 1024 threads):
//   phase A: fused softmax/conf/argmax pass (grid-stride, warp per row)
//   phases 1-8: histogram quantiles -> edges -> bin stats -> final scalar,
//   separated by software grid barriers. Graph = memset + 1 kernel.
// ---------------------------------------------------------------------------

#define NC      100
#define NBINS   15
#define HSIZE   (1 << 18)            // conf in (0,1] -> bits>>12 < 0x40000
#define CHUNK   1024
#define NCHUNK  (HSIZE / CHUNK)      // 256
#define NRANK   32                   // 16 edges x (i, i+1) rank pairs
#define NMAX    500000
#define TB      148                  // blocks (<= SM count: all co-resident)
#define TT      1024                 // threads per block

struct ZeroBlock {
    unsigned hist[HSIZE];
    unsigned subhist[NRANK * 4096];
    double   wnum[NBINS];
    double   total;
    unsigned cnt[NBINS];
};
__device__ ZeroBlock gz;

__device__ float    g_conf_t[NMAX];
__device__ float    g_conf_s[NMAX];
__device__ float    g_wper[NMAX];
__device__ unsigned g_csum[NCHUNK];
__device__ int      g_rankBin[NRANK];
__device__ unsigned g_rankBase[NRANK];
__device__ float    g_srt[NRANK];
__device__ unsigned g_sync_cnt;      // monotonic grid-barrier ticket (never reset)

// --------------------------- grid barrier -----------------------------------
__device__ __forceinline__ void grid_sync() {
    __syncthreads();
    if (threadIdx.x == 0) {
        __threadfence();                                   // release my writes
        unsigned ticket = atomicAdd(&g_sync_cnt, 1u);
        unsigned target = (ticket / TB + 1u) * TB;
        unsigned v;
        do {
            asm volatile("ld.acquire.gpu.u32 %0, [%1];"
                         : "=r"(v) : "l"(&g_sync_cnt));
        } while (v < target);
    }
    __syncthreads();
}

// rank (0-indexed order statistic) needed for edge pair t: (i, i+1), clamped.
__device__ __forceinline__ long long rank_for(int t, int nt) {
    int k = t >> 1;
    double xq = (double)k * (double)nt / 15.0;
    long long i = (long long)floor(xq);
    if (i > (long long)nt - 1) i = (long long)nt - 1;
    long long r = i + (t & 1);
    if (r > (long long)nt - 1) r = (long long)nt - 1;
    return r;
}

// Inclusive block scan over 1024 threads (32 warps). All threads must call.
__device__ __forceinline__ unsigned blockScan1024(unsigned v, unsigned* sh) {
    int tid = threadIdx.x, lane = tid & 31, w = tid >> 5;
    unsigned sc = v;
#pragma unroll
    for (int o = 1; o < 32; o <<= 1) {
        unsigned u = __shfl_up_sync(0xffffffffu, sc, o);
        if (lane >= o) sc += u;
    }
    if (lane == 31) sh[w] = sc;
    __syncthreads();
    if (w == 0) {
        unsigned t = sh[lane];
#pragma unroll
        for (int o = 1; o < 32; o <<= 1) {
            unsigned u = __shfl_up_sync(0xffffffffu, t, o);
            if (lane >= o) t += u;
        }
        sh[lane] = t;
    }
    __syncthreads();
    return sc + (w ? sh[w - 1] : 0u);
}

__global__ void __launch_bounds__(TT, 1)
k_all(const float* __restrict__ lg_t, const float* __restrict__ lg_s,
      const void* __restrict__ labels, const float* __restrict__ wt,
      float* __restrict__ out, int nt, int ns) {
    __shared__ unsigned s_cpref[NCHUNK + 1];
    __shared__ unsigned s_sh[32];
    __shared__ int      s_cIdx;
    __shared__ int      s_first;
    __shared__ int      s_lab64;
    __shared__ float    s_e[16];
    __shared__ float    s_wn[NBINS];
    __shared__ unsigned s_ct[NBINS];
    __shared__ int      s_bins[NRANK];
    __shared__ double   s_ws[32];

    const int tid  = threadIdx.x;
    const int bid  = blockIdx.x;
    const int lane = tid & 31;
    const int wid  = tid >> 5;
    const int gstride = TB * TT;
    const int gtid    = bid * TT + tid;

    // ---- Phase 0 (per-block, no sync): labels dtype detect ----
    if (wid == 0) {
        const unsigned* lb = (const unsigned*)labels;
        unsigned v = lb[2 * lane + 1] | lb[2 * lane + 65];
        unsigned mask = __ballot_sync(0xffffffffu, v != 0u);
        if (lane == 0) s_lab64 = (mask == 0u) ? 1 : 0;
    }
    __syncthreads();
    const int lab64 = s_lab64;

    // ---- Phase A: fused conf pass, one warp per row, grid-stride ----
    {
        const int nWarps = TB * (TT / 32);
        int gwarp = bid * (TT / 32) + wid;
        int rows = nt + ns;
        for (int r = gwarp; r < rows; r += nWarps) {
            bool isT = r < nt;
            int row  = isT ? r : r - nt;
            const float4* p = (const float4*)((isT ? lg_t : lg_s) + (size_t)row * NC);
            float4 v;
            if (lane < 25) v = p[lane];
            else           v = make_float4(-FLT_MAX, -FLT_MAX, -FLT_MAX, -FLT_MAX);

            float m = fmaxf(fmaxf(v.x, v.y), fmaxf(v.z, v.w));
#pragma unroll
            for (int o = 16; o; o >>= 1) m = fmaxf(m, __shfl_xor_sync(0xffffffffu, m, o));

            float s = 0.0f;
            if (lane < 25)
                s = __expf(v.x - m) + __expf(v.y - m) + __expf(v.z - m) + __expf(v.w - m);
#pragma unroll
            for (int o = 16; o; o >>= 1) s += __shfl_xor_sync(0xffffffffu, s, o);

            if (isT) {
                if (lane == 0) {
                    float c = 1.0f / s;
                    g_conf_t[row] = c;
                    atomicAdd(&gz.hist[__float_as_uint(c) >> 12], 1u);
                }
            } else {
                int loc = 127;
                if (lane < 25) {
                    if (v.w == m) loc = 4 * lane + 3;
                    if (v.z == m) loc = 4 * lane + 2;
                    if (v.y == m) loc = 4 * lane + 1;
                    if (v.x == m) loc = 4 * lane;
                }
                unsigned mask = __ballot_sync(0xffffffffu, loc < 127);
                int src = __ffs(mask) - 1;
                int bi  = __shfl_sync(0xffffffffu, loc, src);
                if (lane == 0) {
                    g_conf_s[row] = 1.0f / s;
                    long long lab = lab64 ? ((const long long*)labels)[row]
                                          : (long long)((const int*)labels)[row];
                    g_wper[row] = (bi == (int)lab) ? wt[lab] : 0.0f;
                }
            }
        }
    }
    grid_sync();   // (1)

    // ---- Phase 1: per-chunk sums of coarse histogram ----
    for (int c = bid; c < NCHUNK; c += TB) {
        unsigned s = gz.hist[c * CHUNK + tid];
#pragma unroll
        for (int o = 16; o; o >>= 1) s += __shfl_xor_sync(0xffffffffu, s, o);
        if (lane == 0) s_sh[wid] = s;
        __syncthreads();
        if (wid == 0) {
            unsigned r2 = s_sh[lane];
#pragma unroll
            for (int o = 16; o; o >>= 1) r2 += __shfl_xor_sync(0xffffffffu, r2, o);
            if (lane == 0) g_csum[c] = r2;
        }
        __syncthreads();
    }
    grid_sync();   // (2)

    // ---- Phase 2: rank location (blocks 0..31) ----
    if (bid < NRANK) {
        if (tid == 0) s_first = 1 << 30;
        if (tid < 32) {
            unsigned pre[8]; unsigned run = 0;
#pragma unroll
            for (int j = 0; j < 8; j++) { unsigned h = g_csum[tid * 8 + j]; pre[j] = run; run += h; }
            unsigned sc = run;
#pragma unroll
            for (int o = 1; o < 32; o <<= 1) {
                unsigned u = __shfl_up_sync(0xffffffffu, sc, o);
                if (tid >= o) sc += u;
            }
            unsigned excl = sc - run;
#pragma unroll
            for (int j = 0; j < 8; j++) s_cpref[tid * 8 + j] = excl + pre[j];
            if (tid == 31) s_cpref[NCHUNK] = excl + run;
        }
        __syncthreads();
        unsigned r = (unsigned)rank_for(bid, nt);
        if (tid < NCHUNK && s_cpref[tid] <= r && r < s_cpref[tid + 1]) s_cIdx = tid;
        __syncthreads();
        int c = s_cIdx;
        unsigned h = gz.hist[c * CHUNK + tid];
        unsigned incl = blockScan1024(h, s_sh);
        unsigned cum0 = s_cpref[c];
        if (cum0 + incl > r) atomicMin(&s_first, tid);
        __syncthreads();
        if (tid == s_first) {
            g_rankBin[bid]  = c * CHUNK + tid;
            g_rankBase[bid] = cum0 + incl - h;
        }
    }
    grid_sync();   // (3)

    // ---- Phase 3: refine sub-histograms (all blocks) ----
    if (tid < NRANK) s_bins[tid] = g_rankBin[tid];
    __syncthreads();
    {
        int bmin = 0x7fffffff, bmax = -1;
#pragma unroll
        for (int t = 0; t < NRANK; t++) {
            int b = s_bins[t];
            bmin = min(bmin, b); bmax = max(bmax, b);
        }
        for (int i = gtid; i < nt; i += gstride) {
            unsigned key = __float_as_uint(g_conf_t[i]);
            int bbin = (int)(key >> 12);
            if (bbin < bmin || bbin > bmax) continue;
            unsigned low = key & 4095u;
#pragma unroll
            for (int t = 0; t < NRANK; t++)
                if (s_bins[t] == bbin) atomicAdd(&gz.subhist[t * 4096 + low], 1u);
        }
    }
    grid_sync();   // (4)

    // ---- Phase 4: select exact order statistics (blocks 0..31) ----
    if (bid < NRANK) {
        if (tid == 0) s_first = 1 << 30;
        __syncthreads();
        unsigned target = (unsigned)(rank_for(bid, nt) - (long long)g_rankBase[bid]);
        unsigned h[4], tsum = 0;
        const unsigned* hp = &gz.subhist[bid * 4096 + tid * 4];
#pragma unroll
        for (int j = 0; j < 4; j++) { h[j] = hp[j]; tsum += h[j]; }
        unsigned incl = blockScan1024(tsum, s_sh);
        unsigned cc = incl - tsum;
        int found = -1;
#pragma unroll
        for (int j = 0; j < 4; j++) {
            if (found < 0 && cc + h[j] > target) found = tid * 4 + j;
            cc += h[j];
        }
        if (found >= 0) atomicMin(&s_first, found);
        __syncthreads();
        if (tid == 0)
            g_srt[bid] = __uint_as_float(((unsigned)g_rankBin[bid] << 12) | (unsigned)s_first);
    }
    grid_sync();   // (5)

    // ---- Phase 5 (per-block, no extra sync): edges from order statistics ----
    if (tid < 16) {
        int k = tid; float e;
        if (k == 0)       e = g_srt[0];
        else if (k == 15) e = g_srt[31];
        else {
            double xq = (double)k * (double)nt / 15.0;
            long long i = (long long)floor(xq);
            double frac = xq - (double)i;
            double a = g_srt[2 * k], b2 = g_srt[2 * k + 1];
            e = (float)(a + frac * (b2 - a));
        }
        s_e[k] = e;
    }
    if (tid < NBINS) { s_wn[tid] = 0.0f; s_ct[tid] = 0u; }
    __syncthreads();

    // ---- Phase 6: bin accumulation (half the blocks source, half target) ----
    if (bid < TB / 2) {
        int stride = (TB / 2) * TT;
        for (int i = bid * TT + tid; i < ns; i += stride) {
            float w = g_wper[i];
            if (w != 0.0f) {
                float c = g_conf_s[i];
                if (c > s_e[0] && c <= s_e[15]) {
#pragma unroll
                    for (int b = 0; b < NBINS; b++)
                        if (c <= s_e[b + 1]) { atomicAdd(&s_wn[b], w); break; }
                }
            }
        }
    } else {
        int nb = TB - TB / 2;
        int stride = nb * TT;
        for (int i = (bid - TB / 2) * TT + tid; i < nt; i += stride) {
            float c = g_conf_t[i];
            if (c > s_e[0] && c <= s_e[15]) {
#pragma unroll
                for (int b = 0; b < NBINS; b++)
                    if (c <= s_e[b + 1]) { atomicAdd(&s_ct[b], 1u); break; }
            }
        }
    }
    __syncthreads();
    if (tid < NBINS) {
        if (s_wn[tid] != 0.0f) atomicAdd(&gz.wnum[tid], (double)s_wn[tid]);
        if (s_ct[tid])         atomicAdd(&gz.cnt[tid], s_ct[tid]);
    }
    grid_sync();   // (6)

    // ---- Phase 7 (per-block): cond_expect + ok flags, then diff sum ----
    {
        float ce[NBINS]; bool ok[NBINS];
        double normal = (double)(nt - 1) / (double)ns;
#pragma unroll
        for (int b = 0; b < NBINS; b++) {
            long long ct = (long long)gz.cnt[b];
            long long d  = ct - 1; if (d < 1) d = 1;
            ce[b] = (float)(normal * gz.wnum[b] / (double)d);
            ok[b] = (ct > 1);
        }
        double local = 0.0;
        for (int i = gtid; i < nt; i += gstride) {
            float c = g_conf_t[i];
            if (c > s_e[0] && c <= s_e[15]) {
#pragma unroll
                for (int b = 0; b < NBINS; b++)
                    if (c <= s_e[b + 1]) {
                        if (ok[b]) { float d = c - ce[b]; local += (double)d * (double)d; }
                        break;
                    }
            }
        }
#pragma unroll
        for (int o = 16; o; o >>= 1) local += __shfl_down_sync(0xffffffffu, local, o);
        if (lane == 0) s_ws[wid] = local;
        __syncthreads();
        if (wid == 0) {
            double v = s_ws[lane];
#pragma unroll
            for (int o = 16; o; o >>= 1) v += __shfl_down_sync(0xffffffffu, v, o);
            if (lane == 0) atomicAdd(&gz.total, v);
        }
    }
    grid_sync();   // (7)

    // ---- Phase 8: final scalar ----
    if (bid == 0 && tid == 0) out[0] = (float)(gz.total / (double)nt);
}

extern "C" void kernel_launch(void* const* d_in, const int* in_sizes, int n_in,
                              void* d_out, int out_size) {
    const float* lg_s = (const float*)d_in[0];
    const void*  lab  = d_in[1];
    const float* lg_t = (const float*)d_in[2];
    const float* wt   = (const float*)d_in[3];
    int ns = in_sizes[0] / NC;
    int nt = in_sizes[2] / NC;

    void* zp = nullptr;
    cudaGetSymbolAddress(&zp, gz);
    cudaMemsetAsync(zp, 0, sizeof(ZeroBlock), 0);

    k_all<<<TB, TT>>>(lg_t, lg_s, lab, wt, (float*)d_out, nt, ns);
    (void)n_in; (void)out_size;
}

// round 15
// speedup vs baseline: 2.7462x; 2.7462x over previous
#include <cuda_runtime.h>
#include <math.h>
#include <float.h>

// ---------------------------------------------------------------------------
// EceLabelShift: equal-mass-bin ECE with label-shift weighting.
// R14: conf pass rebuilt as 4-rows-per-warp / 8-lanes-per-row (3-4x MLP,
//      3-step reductions); label-dtype detect folded into conf preamble;
//      tail = proven R9 multi-kernel pipeline.
// ---------------------------------------------------------------------------

#define NC      100
#define NBINS   15
#define HSIZE   (1 << 18)            // conf in (0,1] -> bits>>12 < 0x40000
#define CHUNK   1024
#define NCHUNK  (HSIZE / CHUNK)      // 256
#define NRANK   32                   // 16 edges x (i, i+1) rank pairs
#define NMAX    500000

struct ZeroBlock {
    unsigned hist[HSIZE];
    unsigned subhist[NRANK * 4096];
    double   wnum[NBINS];
    double   total;
    unsigned cnt[NBINS];
};
__device__ ZeroBlock gz;

__device__ float    g_conf_t[NMAX];
__device__ float    g_conf_s[NMAX];
__device__ float    g_wper[NMAX];
__device__ unsigned g_csum[NCHUNK];
__device__ int      g_rankBin[NRANK];
__device__ unsigned g_rankBase[NRANK];
__device__ float    g_srt[NRANK];
__device__ float    g_edges[16];
__device__ float    g_ce[NBINS];
__device__ unsigned char g_cntok[NBINS];

// rank (0-indexed order statistic) needed for edge pair t: (i, i+1), clamped.
__device__ __forceinline__ long long rank_for(int t, int nt) {
    int k = t >> 1;
    double xq = (double)k * (double)nt / 15.0;
    long long i = (long long)floor(xq);
    if (i > (long long)nt - 1) i = (long long)nt - 1;
    long long r = i + (t & 1);
    if (r > (long long)nt - 1) r = (long long)nt - 1;
    return r;
}

// Block-wide (1024 thr = 32 warps) inclusive scan of one unsigned per thread.
__device__ __forceinline__ unsigned blockScanIncl(unsigned v, unsigned* sh) {
    int tid = threadIdx.x, lane = tid & 31, w = tid >> 5;
    unsigned sc = v;
#pragma unroll
    for (int o = 1; o < 32; o <<= 1) {
        unsigned u = __shfl_up_sync(0xffffffffu, sc, o);
        if (lane >= o) sc += u;
    }
    if (lane == 31) sh[w] = sc;
    __syncthreads();
    if (w == 0) {
        unsigned t = sh[lane];
#pragma unroll
        for (int o = 1; o < 32; o <<= 1) {
            unsigned u = __shfl_up_sync(0xffffffffu, t, o);
            if (lane >= o) t += u;
        }
        sh[lane] = t;
    }
    __syncthreads();
    unsigned off = w ? sh[w - 1] : 0u;
    return sc + off;
}

// ---------------------------------------------------------------------------
// Conf pass: 4 rows per warp, 8 lanes per row. Rows [0,nt) = target,
// [nt, nt+ns) = source. Label dtype detected per-block (warp 0 preamble).
// ---------------------------------------------------------------------------
__global__ void __launch_bounds__(256) k_conf(
    const float* __restrict__ lg_t, const float* __restrict__ lg_s,
    const void* __restrict__ labels, const float* __restrict__ wt,
    int nt, int ns) {
    __shared__ int s_lab64;
    const int tid = threadIdx.x, lane = tid & 31, wid = tid >> 5;

    if (tid < 32) {   // int64 labels => odd 32-bit words of first 64 entries 0
        const unsigned* lb = (const unsigned*)labels;
        unsigned v = lb[2 * lane + 1] | lb[2 * lane + 65];
        unsigned mask = __ballot_sync(0xffffffffu, v != 0u);
        if (lane == 0) s_lab64 = (mask == 0u) ? 1 : 0;
    }
    __syncthreads();
    const int lab64 = s_lab64;

    const int sub = lane & 7;            // position within row (8 lanes/row)
    const int g   = lane >> 3;           // which of the warp's 4 rows
    const int rows = nt + ns;
    int r = (blockIdx.x * (blockDim.x >> 5) + wid) * 4 + g;
    bool valid = r < rows;
    bool isT   = r < nt;
    int  row   = isT ? r : r - nt;

    const float4* p = nullptr;
    if (valid) p = (const float4*)((isT ? lg_t : lg_s) + (size_t)row * NC);

    float4 v0, v1, v2, v3;
    const float4 neg = make_float4(-FLT_MAX, -FLT_MAX, -FLT_MAX, -FLT_MAX);
    if (valid) {
        v0 = p[sub]; v1 = p[sub + 8]; v2 = p[sub + 16];
        v3 = (sub == 0) ? p[24] : neg;
    } else { v0 = v1 = v2 = v3 = neg; }

    // row max (3-step reduce within the 8-lane group)
    float m = fmaxf(fmaxf(fmaxf(v0.x, v0.y), fmaxf(v0.z, v0.w)),
              fmaxf(fmaxf(fmaxf(v1.x, v1.y), fmaxf(v1.z, v1.w)),
              fmaxf(fmaxf(fmaxf(v2.x, v2.y), fmaxf(v2.z, v2.w)),
                    fmaxf(fmaxf(v3.x, v3.y), fmaxf(v3.z, v3.w)))));
#pragma unroll
    for (int o = 4; o; o >>= 1) m = fmaxf(m, __shfl_xor_sync(0xffffffffu, m, o));

    // row sum of exp(v - m)
    float s = 0.0f;
    if (valid) {
        s  = __expf(v0.x - m) + __expf(v0.y - m) + __expf(v0.z - m) + __expf(v0.w - m);
        s += __expf(v1.x - m) + __expf(v1.y - m) + __expf(v1.z - m) + __expf(v1.w - m);
        s += __expf(v2.x - m) + __expf(v2.y - m) + __expf(v2.z - m) + __expf(v2.w - m);
        if (sub == 0)
            s += __expf(v3.x - m) + __expf(v3.y - m) + __expf(v3.z - m) + __expf(v3.w - m);
    }
#pragma unroll
    for (int o = 4; o; o >>= 1) s += __shfl_xor_sync(0xffffffffu, s, o);

    if (isT) {
        if (valid && sub == 0) {
            float c = 1.0f / s;
            g_conf_t[row] = c;
            atomicAdd(&gz.hist[__float_as_uint(c) >> 12], 1u);
        }
    } else {
        // first-occurrence argmax: per-lane smallest own index with value == m
        int loc = 1 << 30;
        if (valid) {
            if (sub == 0) {                       // cols 96..99 (highest)
                if (v3.w == m) loc = 99;
                if (v3.z == m) loc = 98;
                if (v3.y == m) loc = 97;
                if (v3.x == m) loc = 96;
            }
            int b2 = 64 + 4 * sub;
            if (v2.w == m) loc = b2 + 3;
            if (v2.z == m) loc = b2 + 2;
            if (v2.y == m) loc = b2 + 1;
            if (v2.x == m) loc = b2;
            int b1 = 32 + 4 * sub;
            if (v1.w == m) loc = b1 + 3;
            if (v1.z == m) loc = b1 + 2;
            if (v1.y == m) loc = b1 + 1;
            if (v1.x == m) loc = b1;
            int b0 = 4 * sub;
            if (v0.w == m) loc = b0 + 3;
            if (v0.z == m) loc = b0 + 2;
            if (v0.y == m) loc = b0 + 1;
            if (v0.x == m) loc = b0;
        }
#pragma unroll
        for (int o = 4; o; o >>= 1) loc = min(loc, __shfl_xor_sync(0xffffffffu, loc, o));
        if (valid && sub == 0) {
            g_conf_s[row] = 1.0f / s;
            long long lab = lab64 ? ((const long long*)labels)[row]
                                  : (long long)((const int*)labels)[row];
            g_wper[row] = (loc == (int)lab) ? wt[lab] : 0.0f;
        }
    }
}

// Per-chunk sums of the coarse histogram (grid = NCHUNK blocks).
__global__ void k_csum() {
    int c = blockIdx.x, tid = threadIdx.x;   // 256 threads
    unsigned s = 0;
#pragma unroll
    for (int j = 0; j < CHUNK / 256; j++) s += gz.hist[c * CHUNK + j * 256 + tid];
#pragma unroll
    for (int o = 16; o; o >>= 1) s += __shfl_xor_sync(0xffffffffu, s, o);
    __shared__ unsigned ws[8];
    if ((tid & 31) == 0) ws[tid >> 5] = s;
    __syncthreads();
    if (tid < 8) {
        unsigned v = ws[tid];
#pragma unroll
        for (int o = 4; o; o >>= 1) v += __shfl_xor_sync(0xffu, v, o);
        if (tid == 0) g_csum[c] = v;
    }
}

// One block per rank: prefix over chunk sums, locate chunk, block-scan chunk.
__global__ void k_rank(int nt) {
    __shared__ unsigned cpref[NCHUNK + 1];
    __shared__ unsigned sh[32];
    __shared__ int cIdx;
    __shared__ int firstIdx;
    int tid = threadIdx.x, b = blockIdx.x;
    if (tid == 0) firstIdx = 1 << 30;
    if (tid < 32) {
        unsigned s[8]; unsigned run = 0;
#pragma unroll
        for (int j = 0; j < 8; j++) { unsigned h = g_csum[tid * 8 + j]; s[j] = run; run += h; }
        unsigned sc = run;
#pragma unroll
        for (int o = 1; o < 32; o <<= 1) {
            unsigned u = __shfl_up_sync(0xffffffffu, sc, o);
            if (tid >= o) sc += u;
        }
        unsigned excl = sc - run;
#pragma unroll
        for (int j = 0; j < 8; j++) cpref[tid * 8 + j] = excl + s[j];
        if (tid == 31) cpref[NCHUNK] = excl + run;
    }
    __syncthreads();
    unsigned r = (unsigned)rank_for(b, nt);
    if (tid < NCHUNK && cpref[tid] <= r && r < cpref[tid + 1]) cIdx = tid;
    __syncthreads();
    int c = cIdx;
    unsigned h = gz.hist[c * CHUNK + tid];
    unsigned incl = blockScanIncl(h, sh);
    unsigned cum0 = cpref[c];
    if (cum0 + incl > r) atomicMin(&firstIdx, tid);
    __syncthreads();
    if (tid == firstIdx) {
        g_rankBin[b]  = c * CHUNK + tid;
        g_rankBase[b] = cum0 + incl - h;
    }
}

// Sub-histogram (low 12 key bits) for each rank's coarse bin.
__global__ void k_refine(int nt) {
    __shared__ int sb[NRANK];
    if (threadIdx.x < NRANK) sb[threadIdx.x] = g_rankBin[threadIdx.x];
    __syncthreads();
    int myb[NRANK];
    int bmin = 0x7fffffff, bmax = -1;
#pragma unroll
    for (int t = 0; t < NRANK; t++) {
        myb[t] = sb[t];
        bmin = min(bmin, myb[t]); bmax = max(bmax, myb[t]);
    }
    int stride = gridDim.x * blockDim.x;
    for (int i = blockIdx.x * blockDim.x + threadIdx.x; i < nt; i += stride) {
        unsigned key = __float_as_uint(g_conf_t[i]);
        int bbin = (int)(key >> 12);
        if (bbin < bmin || bbin > bmax) continue;
        unsigned low = key & 4095u;
#pragma unroll
        for (int t = 0; t < NRANK; t++)
            if (myb[t] == bbin) atomicAdd(&gz.subhist[t * 4096 + low], 1u);
    }
}

// One block per rank: block scan of its 4096-bin sub-hist -> exact float.
__global__ void k_select(int nt) {
    __shared__ unsigned sh[32];
    __shared__ int firstIdx;
    int tid = threadIdx.x, b = blockIdx.x;
    if (tid == 0) firstIdx = 1 << 30;
    unsigned target = (unsigned)(rank_for(b, nt) - (long long)g_rankBase[b]);
    unsigned h[4]; unsigned tsum = 0;
    int base = b * 4096 + tid * 4;
#pragma unroll
    for (int j = 0; j < 4; j++) { h[j] = gz.subhist[base + j]; tsum += h[j]; }
    unsigned incl = blockScanIncl(tsum, sh);
    unsigned cum  = incl - tsum;
    int found = -1;
#pragma unroll
    for (int j = 0; j < 4; j++) {
        if (found < 0 && cum + h[j] > target) found = tid * 4 + j;
        cum += h[j];
    }
    if (found >= 0) atomicMin(&firstIdx, found);
    __syncthreads();
    if (tid == 0)
        g_srt[b] = __uint_as_float(((unsigned)g_rankBin[b] << 12) | (unsigned)firstIdx);
}

// Interpolate the 16 equal-mass edges from the 32 order statistics.
__global__ void k_edges(int nt) {
    int k = threadIdx.x;
    if (k < 16) {
        float e;
        if (k == 0)       e = g_srt[0];
        else if (k == 15) e = g_srt[31];
        else {
            double xq = (double)k * (double)nt / 15.0;
            long long i = (long long)floor(xq);
            double frac = xq - (double)i;
            double a = g_srt[2 * k], b2 = g_srt[2 * k + 1];
            e = (float)(a + frac * (b2 - a));
        }
        g_edges[k] = e;
    }
}

// Bin accumulation: blocks [0,srcBlocks) -> weighted_num, rest -> count_t.
__global__ void k_binacc(int ns, int nt, int srcBlocks) {
    __shared__ float    swn[NBINS];
    __shared__ unsigned sct[NBINS];
    int tid = threadIdx.x;
    if (tid < NBINS) { swn[tid] = 0.0f; sct[tid] = 0u; }
    float e[16];
#pragma unroll
    for (int k = 0; k < 16; k++) e[k] = g_edges[k];
    __syncthreads();
    if ((int)blockIdx.x < srcBlocks) {
        int stride = srcBlocks * blockDim.x;
        for (int i = blockIdx.x * blockDim.x + tid; i < ns; i += stride) {
            float w = g_wper[i];
            if (w != 0.0f) {
                float c = g_conf_s[i];
                if (c > e[0] && c <= e[15]) {
#pragma unroll
                    for (int b = 0; b < NBINS; b++)
                        if (c <= e[b + 1]) { atomicAdd(&swn[b], w); break; }
                }
            }
        }
    } else {
        int nb = gridDim.x - srcBlocks;
        int stride = nb * blockDim.x;
        for (int i = ((int)blockIdx.x - srcBlocks) * blockDim.x + tid; i < nt; i += stride) {
            float c = g_conf_t[i];
            if (c > e[0] && c <= e[15]) {
#pragma unroll
                for (int b = 0; b < NBINS; b++)
                    if (c <= e[b + 1]) { atomicAdd(&sct[b], 1u); break; }
            }
        }
    }
    __syncthreads();
    if (tid < NBINS) {
        if (swn[tid] != 0.0f) atomicAdd(&gz.wnum[tid], (double)swn[tid]);
        if (sct[tid])         atomicAdd(&gz.cnt[tid], sct[tid]);
    }
}

__global__ void k_ce(int ns, int nt) {
    int b = threadIdx.x;
    if (b < NBINS) {
        long long ct = (long long)gz.cnt[b];
        long long d  = ct - 1; if (d < 1) d = 1;
        double normal = (double)(nt - 1) / (double)ns;
        g_ce[b]    = (float)(normal * gz.wnum[b] / (double)d);
        g_cntok[b] = (ct > 1) ? 1 : 0;
    }
}

// Sum of (conf_t - cond_expect[bin])^2 over binned target samples.
__global__ void k_diff(int nt) {
    float e[16]; float ce[NBINS]; bool ok[NBINS];
#pragma unroll
    for (int k = 0; k < 16; k++) e[k] = g_edges[k];
#pragma unroll
    for (int k = 0; k < NBINS; k++) { ce[k] = g_ce[k]; ok[k] = (g_cntok[k] != 0); }
    int tid = threadIdx.x;
    double local = 0.0;
    int stride = gridDim.x * blockDim.x;
    for (int i = blockIdx.x * blockDim.x + tid; i < nt; i += stride) {
        float c = g_conf_t[i];
        if (c > e[0] && c <= e[15]) {
#pragma unroll
            for (int b = 0; b < NBINS; b++)
                if (c <= e[b + 1]) {
                    if (ok[b]) { float d = c - ce[b]; local += (double)d * (double)d; }
                    break;
                }
        }
    }
#pragma unroll
    for (int o = 16; o; o >>= 1) local += __shfl_down_sync(0xffffffffu, local, o);
    __shared__ double warpsum[8];
    if ((tid & 31) == 0) warpsum[tid >> 5] = local;
    __syncthreads();
    if (tid < 8) {
        double v = warpsum[tid];
#pragma unroll
        for (int o = 4; o; o >>= 1) v += __shfl_down_sync(0xffu, v, o);
        if (tid == 0) atomicAdd(&gz.total, v);
    }
}

__global__ void k_final(float* out, int nt) {
    out[0] = (float)(gz.total / (double)nt);
}

extern "C" void kernel_launch(void* const* d_in, const int* in_sizes, int n_in,
                              void* d_out, int out_size) {
    const float* lg_s = (const float*)d_in[0];
    const void*  lab  = d_in[1];
    const float* lg_t = (const float*)d_in[2];
    const float* wt   = (const float*)d_in[3];
    int ns = in_sizes[0] / NC;
    int nt = in_sizes[2] / NC;

    void* zp = nullptr;
    cudaGetSymbolAddress(&zp, gz);
    cudaMemsetAsync(zp, 0, sizeof(ZeroBlock), 0);

    int rows = nt + ns;                    // 4 rows/warp, 8 warps/block
    int blocks = (rows + 31) / 32;
    k_conf<<<blocks, 256>>>(lg_t, lg_s, lab, wt, nt, ns);

    k_csum<<<NCHUNK, 256>>>();
    k_rank<<<NRANK, 1024>>>(nt);
    k_refine<<<888, 256>>>(nt);
    k_select<<<NRANK, 1024>>>(nt);
    k_edges<<<1, 32>>>(nt);
    k_binacc<<<1184, 256>>>(ns, nt, 592);
    k_ce<<<1, 32>>>(ns, nt);
    k_diff<<<888, 256>>>(nt);
    k_final<<<1, 1>>>((float*)d_out, nt);
    (void)n_in; (void)out_size;
}

// round 16
// speedup vs baseline: 2.9463x; 1.0729x over previous
#include <cuda_runtime.h>
#include <math.h>
#include <float.h>

// ---------------------------------------------------------------------------
// EceLabelShift: equal-mass-bin ECE with label-shift weighting.
// R15: refine deduped + binary search (1 atomic max/elem), edges/ce folded
//      into consumer preambles (-2 launches), 4-step binning search,
//      (conf_s,wper) packed as float2.
// ---------------------------------------------------------------------------

#define NC      100
#define NBINS   15
#define HSIZE   (1 << 18)            // conf in (0,1] -> bits>>12 < 0x40000
#define CHUNK   1024
#define NCHUNK  (HSIZE / CHUNK)      // 256
#define NRANK   32                   // 16 edges x (i, i+1) rank pairs
#define NMAX    500000

struct ZeroBlock {
    unsigned hist[HSIZE];
    unsigned subhist[NRANK * 4096];
    double   wnum[NBINS];
    double   total;
    unsigned cnt[NBINS];
};
__device__ ZeroBlock gz;

__device__ float    g_conf_t[NMAX];
__device__ float2   g_cs[NMAX];        // (conf_s, wper)
__device__ unsigned g_csum[NCHUNK];
__device__ int      g_rankBin[NRANK];
__device__ unsigned g_rankBase[NRANK];
__device__ float    g_srt[NRANK];

// rank (0-indexed order statistic) needed for edge pair t: (i, i+1), clamped.
__device__ __forceinline__ long long rank_for(int t, int nt) {
    int k = t >> 1;
    double xq = (double)k * (double)nt / 15.0;
    long long i = (long long)floor(xq);
    if (i > (long long)nt - 1) i = (long long)nt - 1;
    long long r = i + (t & 1);
    if (r > (long long)nt - 1) r = (long long)nt - 1;
    return r;
}

// Edge k (k in [0,16)) from the 32 order statistics in g_srt.
__device__ __forceinline__ float edge_for(int k, int nt) {
    if (k == 0)  return g_srt[0];
    if (k == 15) return g_srt[31];
    double xq = (double)k * (double)nt / 15.0;
    long long i = (long long)floor(xq);
    double frac = xq - (double)i;
    double a = g_srt[2 * k], b2 = g_srt[2 * k + 1];
    return (float)(a + frac * (b2 - a));
}

// Block-wide (1024 thr = 32 warps) inclusive scan of one unsigned per thread.
__device__ __forceinline__ unsigned blockScanIncl(unsigned v, unsigned* sh) {
    int tid = threadIdx.x, lane = tid & 31, w = tid >> 5;
    unsigned sc = v;
#pragma unroll
    for (int o = 1; o < 32; o <<= 1) {
        unsigned u = __shfl_up_sync(0xffffffffu, sc, o);
        if (lane >= o) sc += u;
    }
    if (lane == 31) sh[w] = sc;
    __syncthreads();
    if (w == 0) {
        unsigned t = sh[lane];
#pragma unroll
        for (int o = 1; o < 32; o <<= 1) {
            unsigned u = __shfl_up_sync(0xffffffffu, t, o);
            if (lane >= o) t += u;
        }
        sh[lane] = t;
    }
    __syncthreads();
    unsigned off = w ? sh[w - 1] : 0u;
    return sc + off;
}

// ---------------------------------------------------------------------------
// Conf pass: 4 rows per warp, 8 lanes per row. Rows [0,nt) = target,
// [nt, nt+ns) = source. Label dtype detected per-block (warp 0 preamble).
// ---------------------------------------------------------------------------
__global__ void __launch_bounds__(256) k_conf(
    const float* __restrict__ lg_t, const float* __restrict__ lg_s,
    const void* __restrict__ labels, const float* __restrict__ wt,
    int nt, int ns) {
    __shared__ int s_lab64;
    const int tid = threadIdx.x, lane = tid & 31, wid = tid >> 5;

    if (tid < 32) {   // int64 labels => odd 32-bit words of first 64 entries 0
        const unsigned* lb = (const unsigned*)labels;
        unsigned v = lb[2 * lane + 1] | lb[2 * lane + 65];
        unsigned mask = __ballot_sync(0xffffffffu, v != 0u);
        if (lane == 0) s_lab64 = (mask == 0u) ? 1 : 0;
    }
    __syncthreads();
    const int lab64 = s_lab64;

    const int sub = lane & 7;            // position within row (8 lanes/row)
    const int g   = lane >> 3;           // which of the warp's 4 rows
    const int rows = nt + ns;
    int r = (blockIdx.x * (blockDim.x >> 5) + wid) * 4 + g;
    bool valid = r < rows;
    bool isT   = r < nt;
    int  row   = isT ? r : r - nt;

    const float4* p = nullptr;
    if (valid) p = (const float4*)((isT ? lg_t : lg_s) + (size_t)row * NC);

    float4 v0, v1, v2, v3;
    const float4 neg = make_float4(-FLT_MAX, -FLT_MAX, -FLT_MAX, -FLT_MAX);
    if (valid) {
        v0 = p[sub]; v1 = p[sub + 8]; v2 = p[sub + 16];
        v3 = (sub == 0) ? p[24] : neg;
    } else { v0 = v1 = v2 = v3 = neg; }

    // row max (3-step reduce within the 8-lane group)
    float m = fmaxf(fmaxf(fmaxf(v0.x, v0.y), fmaxf(v0.z, v0.w)),
              fmaxf(fmaxf(fmaxf(v1.x, v1.y), fmaxf(v1.z, v1.w)),
              fmaxf(fmaxf(fmaxf(v2.x, v2.y), fmaxf(v2.z, v2.w)),
                    fmaxf(fmaxf(v3.x, v3.y), fmaxf(v3.z, v3.w)))));
#pragma unroll
    for (int o = 4; o; o >>= 1) m = fmaxf(m, __shfl_xor_sync(0xffffffffu, m, o));

    // row sum of exp(v - m)
    float s = 0.0f;
    if (valid) {
        s  = __expf(v0.x - m) + __expf(v0.y - m) + __expf(v0.z - m) + __expf(v0.w - m);
        s += __expf(v1.x - m) + __expf(v1.y - m) + __expf(v1.z - m) + __expf(v1.w - m);
        s += __expf(v2.x - m) + __expf(v2.y - m) + __expf(v2.z - m) + __expf(v2.w - m);
        if (sub == 0)
            s += __expf(v3.x - m) + __expf(v3.y - m) + __expf(v3.z - m) + __expf(v3.w - m);
    }
#pragma unroll
    for (int o = 4; o; o >>= 1) s += __shfl_xor_sync(0xffffffffu, s, o);

    if (isT) {
        if (valid && sub == 0) {
            float c = 1.0f / s;
            g_conf_t[row] = c;
            atomicAdd(&gz.hist[__float_as_uint(c) >> 12], 1u);
        }
    } else {
        // first-occurrence argmax: per-lane smallest own index with value == m
        int loc = 1 << 30;
        if (valid) {
            if (sub == 0) {                       // cols 96..99 (highest)
                if (v3.w == m) loc = 99;
                if (v3.z == m) loc = 98;
                if (v3.y == m) loc = 97;
                if (v3.x == m) loc = 96;
            }
            int b2 = 64 + 4 * sub;
            if (v2.w == m) loc = b2 + 3;
            if (v2.z == m) loc = b2 + 2;
            if (v2.y == m) loc = b2 + 1;
            if (v2.x == m) loc = b2;
            int b1 = 32 + 4 * sub;
            if (v1.w == m) loc = b1 + 3;
            if (v1.z == m) loc = b1 + 2;
            if (v1.y == m) loc = b1 + 1;
            if (v1.x == m) loc = b1;
            int b0 = 4 * sub;
            if (v0.w == m) loc = b0 + 3;
            if (v0.z == m) loc = b0 + 2;
            if (v0.y == m) loc = b0 + 1;
            if (v0.x == m) loc = b0;
        }
#pragma unroll
        for (int o = 4; o; o >>= 1) loc = min(loc, __shfl_xor_sync(0xffffffffu, loc, o));
        if (valid && sub == 0) {
            long long lab = lab64 ? ((const long long*)labels)[row]
                                  : (long long)((const int*)labels)[row];
            float w = (loc == (int)lab) ? wt[lab] : 0.0f;
            g_cs[row] = make_float2(1.0f / s, w);
        }
    }
}

// Per-chunk sums of the coarse histogram (grid = NCHUNK blocks).
__global__ void k_csum() {
    int c = blockIdx.x, tid = threadIdx.x;   // 256 threads
    unsigned s = 0;
#pragma unroll
    for (int j = 0; j < CHUNK / 256; j++) s += gz.hist[c * CHUNK + j * 256 + tid];
#pragma unroll
    for (int o = 16; o; o >>= 1) s += __shfl_xor_sync(0xffffffffu, s, o);
    __shared__ unsigned ws[8];
    if ((tid & 31) == 0) ws[tid >> 5] = s;
    __syncthreads();
    if (tid < 8) {
        unsigned v = ws[tid];
#pragma unroll
        for (int o = 4; o; o >>= 1) v += __shfl_xor_sync(0xffu, v, o);
        if (tid == 0) g_csum[c] = v;
    }
}

// One block per rank: prefix over chunk sums, locate chunk, block-scan chunk.
__global__ void k_rank(int nt) {
    __shared__ unsigned cpref[NCHUNK + 1];
    __shared__ unsigned sh[32];
    __shared__ int cIdx;
    __shared__ int firstIdx;
    int tid = threadIdx.x, b = blockIdx.x;
    if (tid == 0) firstIdx = 1 << 30;
    if (tid < 32) {
        unsigned s[8]; unsigned run = 0;
#pragma unroll
        for (int j = 0; j < 8; j++) { unsigned h = g_csum[tid * 8 + j]; s[j] = run; run += h; }
        unsigned sc = run;
#pragma unroll
        for (int o = 1; o < 32; o <<= 1) {
            unsigned u = __shfl_up_sync(0xffffffffu, sc, o);
            if (tid >= o) sc += u;
        }
        unsigned excl = sc - run;
#pragma unroll
        for (int j = 0; j < 8; j++) cpref[tid * 8 + j] = excl + s[j];
        if (tid == 31) cpref[NCHUNK] = excl + run;
    }
    __syncthreads();
    unsigned r = (unsigned)rank_for(b, nt);
    if (tid < NCHUNK && cpref[tid] <= r && r < cpref[tid + 1]) cIdx = tid;
    __syncthreads();
    int c = cIdx;
    unsigned h = gz.hist[c * CHUNK + tid];
    unsigned incl = blockScanIncl(h, sh);
    unsigned cum0 = cpref[c];
    if (cum0 + incl > r) atomicMin(&firstIdx, tid);
    __syncthreads();
    if (tid == firstIdx) {
        g_rankBin[b]  = c * CHUNK + tid;
        g_rankBase[b] = cum0 + incl - h;
    }
}

// Sub-histogram for UNIQUE rank bins (g_rankBin is non-decreasing):
// binary search the deduped sorted list; at most one atomic per element.
__global__ void k_refine(int nt) {
    __shared__ int ub[NRANK];
    __shared__ int s_nu;
    int tid = threadIdx.x;
    if (tid == 0) {
        int nu = 0, prev = -1;
#pragma unroll
        for (int t = 0; t < NRANK; t++) {
            int b = g_rankBin[t];
            if (b != prev) { ub[nu++] = b; prev = b; }
        }
        s_nu = nu;
    }
    __syncthreads();
    const int nu = s_nu;
    const int bmin = ub[0], bmax = ub[nu - 1];
    int stride = gridDim.x * blockDim.x;
    for (int i = blockIdx.x * blockDim.x + tid; i < nt; i += stride) {
        unsigned key = __float_as_uint(g_conf_t[i]);
        int bbin = (int)(key >> 12);
        if (bbin < bmin || bbin > bmax) continue;
        int lo = 0, hi = nu;
        while (lo < hi) { int mid = (lo + hi) >> 1; if (ub[mid] < bbin) lo = mid + 1; else hi = mid; }
        if (lo < nu && ub[lo] == bbin)
            atomicAdd(&gz.subhist[lo * 4096 + (key & 4095u)], 1u);
    }
}

// One block per rank: block scan of its (deduped) sub-hist -> exact float.
__global__ void k_select(int nt) {
    __shared__ unsigned sh[32];
    __shared__ int firstIdx;
    __shared__ int s_slot;
    int tid = threadIdx.x, b = blockIdx.x;
    if (tid == 0) {
        firstIdx = 1 << 30;
        int nu = 0, prev = -1, slot = 0;
#pragma unroll
        for (int t = 0; t < NRANK; t++) {
            int bb = g_rankBin[t];
            if (bb != prev) { prev = bb; nu++; }
            if (t == b) slot = nu - 1;
        }
        s_slot = slot;
    }
    __syncthreads();
    unsigned target = (unsigned)(rank_for(b, nt) - (long long)g_rankBase[b]);
    unsigned h[4]; unsigned tsum = 0;
    int base = s_slot * 4096 + tid * 4;
#pragma unroll
    for (int j = 0; j < 4; j++) { h[j] = gz.subhist[base + j]; tsum += h[j]; }
    unsigned incl = blockScanIncl(tsum, sh);
    unsigned cum  = incl - tsum;
    int found = -1;
#pragma unroll
    for (int j = 0; j < 4; j++) {
        if (found < 0 && cum + h[j] > target) found = tid * 4 + j;
        cum += h[j];
    }
    if (found >= 0) atomicMin(&firstIdx, found);
    __syncthreads();
    if (tid == 0)
        g_srt[b] = __uint_as_float(((unsigned)g_rankBin[b] << 12) | (unsigned)firstIdx);
}

// Bin accumulation: blocks [0,srcBlocks) -> weighted_num, rest -> count_t.
// Edges computed per-block from g_srt (no k_edges kernel).
__global__ void k_binacc(int ns, int nt, int srcBlocks) {
    __shared__ float    se[16];
    __shared__ float    swn[NBINS];
    __shared__ unsigned sct[NBINS];
    int tid = threadIdx.x;
    if (tid < 16)    se[tid] = edge_for(tid, nt);
    if (tid < NBINS) { swn[tid] = 0.0f; sct[tid] = 0u; }
    __syncthreads();
    if ((int)blockIdx.x < srcBlocks) {
        int stride = srcBlocks * blockDim.x;
        for (int i = blockIdx.x * blockDim.x + tid; i < ns; i += stride) {
            float2 cw = g_cs[i];
            if (cw.y != 0.0f) {
                float c = cw.x;
                if (c > se[0] && c <= se[15]) {
                    int b = 0;
                    if (c > se[8])     b = 8;
                    if (c > se[b + 4]) b += 4;
                    if (c > se[b + 2]) b += 2;
                    if (c > se[b + 1]) b += 1;
                    atomicAdd(&swn[b], cw.y);
                }
            }
        }
    } else {
        int nb = gridDim.x - srcBlocks;
        int stride = nb * blockDim.x;
        for (int i = ((int)blockIdx.x - srcBlocks) * blockDim.x + tid; i < nt; i += stride) {
            float c = g_conf_t[i];
            if (c > se[0] && c <= se[15]) {
                int b = 0;
                if (c > se[8])     b = 8;
                if (c > se[b + 4]) b += 4;
                if (c > se[b + 2]) b += 2;
                if (c > se[b + 1]) b += 1;
                atomicAdd(&sct[b], 1u);
            }
        }
    }
    __syncthreads();
    if (tid < NBINS) {
        if (swn[tid] != 0.0f) atomicAdd(&gz.wnum[tid], (double)swn[tid]);
        if (sct[tid])         atomicAdd(&gz.cnt[tid], sct[tid]);
    }
}

// Sum of (conf_t - cond_expect[bin])^2; edges + cond_expect in preamble.
__global__ void k_diff(int ns, int nt) {
    __shared__ float se[16];
    __shared__ float sce[NBINS];
    __shared__ unsigned char sok[NBINS];
    int tid = threadIdx.x;
    if (tid < 16) se[tid] = edge_for(tid, nt);
    if (tid < NBINS) {
        long long ct = (long long)gz.cnt[tid];
        long long d  = ct - 1; if (d < 1) d = 1;
        double normal = (double)(nt - 1) / (double)ns;
        sce[tid] = (float)(normal * gz.wnum[tid] / (double)d);
        sok[tid] = (ct > 1) ? 1 : 0;
    }
    __syncthreads();
    double local = 0.0;
    int stride = gridDim.x * blockDim.x;
    for (int i = blockIdx.x * blockDim.x + tid; i < nt; i += stride) {
        float c = g_conf_t[i];
        if (c > se[0] && c <= se[15]) {
            int b = 0;
            if (c > se[8])     b = 8;
            if (c > se[b + 4]) b += 4;
            if (c > se[b + 2]) b += 2;
            if (c > se[b + 1]) b += 1;
            if (sok[b]) { float d = c - sce[b]; local += (double)d * (double)d; }
        }
    }
#pragma unroll
    for (int o = 16; o; o >>= 1) local += __shfl_down_sync(0xffffffffu, local, o);
    __shared__ double warpsum[8];
    if ((tid & 31) == 0) warpsum[tid >> 5] = local;
    __syncthreads();
    if (tid < 8) {
        double v = warpsum[tid];
#pragma unroll
        for (int o = 4; o; o >>= 1) v += __shfl_down_sync(0xffu, v, o);
        if (tid == 0) atomicAdd(&gz.total, v);
    }
}

__global__ void k_final(float* out, int nt) {
    out[0] = (float)(gz.total / (double)nt);
}

extern "C" void kernel_launch(void* const* d_in, const int* in_sizes, int n_in,
                              void* d_out, int out_size) {
    const float* lg_s = (const float*)d_in[0];
    const void*  lab  = d_in[1];
    const float* lg_t = (const float*)d_in[2];
    const float* wt   = (const float*)d_in[3];
    int ns = in_sizes[0] / NC;
    int nt = in_sizes[2] / NC;

    void* zp = nullptr;
    cudaGetSymbolAddress(&zp, gz);
    cudaMemsetAsync(zp, 0, sizeof(ZeroBlock), 0);

    int rows = nt + ns;                    // 4 rows/warp, 8 warps/block
    int blocks = (rows + 31) / 32;
    k_conf<<<blocks, 256>>>(lg_t, lg_s, lab, wt, nt, ns);

    k_csum<<<NCHUNK, 256>>>();
    k_rank<<<NRANK, 1024>>>(nt);
    k_refine<<<888, 256>>>(nt);
    k_select<<<NRANK, 1024>>>(nt);
    k_binacc<<<1184, 256>>>(ns, nt, 592);
    k_diff<<<888, 256>>>(ns, nt);
    k_final<<<1, 1>>>((float*)d_out, nt);
    (void)n_in; (void)out_size;
}